// round 16
// baseline (speedup 1.0000x reference)
#include <cuda_runtime.h>
#include <cuda_bf16.h>
#include <math.h>
#include <cstdint>

#define BB 2048
#define SS 23
#define DD 768
#define HH 8
#define HDD 96
#define LL 50
#define NT 184
#define NTP 192
#define KA 6912
#define NL 64
#define NSPLIT 18

// ---------------- scratch ----------------
__device__ float g_qconst[SS*DD];
__device__ __nv_bfloat16 g_sprojh[NTP*DD];
__device__ float g_c0[NTP];
__device__ float g_Mt[DD*NL];
__device__ float g_bvM[NL];
__device__ float g_boutP[NL];
__device__ float g_msumP[NL];
__device__ float g_scores[(size_t)BB*SS*NTP];
__device__ __nv_bfloat16 g_Ah[(size_t)BB*KA];
__device__ __nv_bfloat16 g_Al[(size_t)BB*KA];
__device__ __nv_bfloat16 g_Wh[(size_t)NL*KA];   // [l][k]
__device__ __nv_bfloat16 g_Wl[(size_t)NL*KA];
__device__ float g_P[(size_t)NSPLIT*BB*NL];
// compaction
__device__ int g_rowidx[BB*SS + 64];
__device__ int g_rowstart[BB];
__device__ int g_nex[BB];
__device__ int g_sqmiss[BB*24];
__device__ int g_mtotal;

// ---------------- helpers ----------------
__device__ __forceinline__ uint32_t smem_u32(const void* p) {
    uint32_t a;
    asm("{ .reg .u64 t; cvta.to.shared.u64 t, %1; cvt.u32.u64 %0, t; }" : "=r"(a) : "l"(p));
    return a;
}
__device__ __forceinline__ void ldsm_x4(uint32_t& r0, uint32_t& r1, uint32_t& r2, uint32_t& r3,
                                        uint32_t addr) {
    asm volatile("ldmatrix.sync.aligned.m8n8.x4.shared.b16 {%0,%1,%2,%3}, [%4];"
                 : "=r"(r0), "=r"(r1), "=r"(r2), "=r"(r3) : "r"(addr));
}
__device__ __forceinline__ void mma_bf16(float* d,
                                         uint32_t a0, uint32_t a1, uint32_t a2, uint32_t a3,
                                         uint32_t b0, uint32_t b1) {
    asm volatile(
        "mma.sync.aligned.m16n8k16.row.col.f32.bf16.bf16.f32 "
        "{%0,%1,%2,%3}, {%4,%5,%6,%7}, {%8,%9}, {%0,%1,%2,%3};"
        : "+f"(d[0]), "+f"(d[1]), "+f"(d[2]), "+f"(d[3])
        : "r"(a0), "r"(a1), "r"(a2), "r"(a3), "r"(b0), "r"(b1));
}
__device__ __forceinline__ uint32_t pack_bf16(float lo, float hi) {
    __nv_bfloat162 v = __floats2bfloat162_rn(lo, hi);
    return *reinterpret_cast<uint32_t*>(&v);
}
__device__ __forceinline__ void split_store4(__nv_bfloat16* ph, __nv_bfloat16* pl, float4 v) {
    __nv_bfloat162 h0 = __floats2bfloat162_rn(v.x, v.y);
    __nv_bfloat162 h1 = __floats2bfloat162_rn(v.z, v.w);
    float2 f0 = __bfloat1622float2(h0);
    float2 f1 = __bfloat1622float2(h1);
    __nv_bfloat162 l0 = __floats2bfloat162_rn(v.x - f0.x, v.y - f0.y);
    __nv_bfloat162 l1 = __floats2bfloat162_rn(v.z - f1.x, v.w - f1.y);
    uint2 uh, ul;
    uh.x = *reinterpret_cast<uint32_t*>(&h0); uh.y = *reinterpret_cast<uint32_t*>(&h1);
    ul.x = *reinterpret_cast<uint32_t*>(&l0); ul.y = *reinterpret_cast<uint32_t*>(&l1);
    *(uint2*)ph = uh;
    *(uint2*)pl = ul;
}

// ================= PRE1: p1_qconst tiled (69) + p3_Mt (64) + nex-count (8) =========
__global__ void __launch_bounds__(256) pre1(const float* __restrict__ mt,
                                            const float* __restrict__ W,
                                            const float* __restrict__ bias,
                                            const float* __restrict__ pw,
                                            const float* __restrict__ ow,
                                            const int* __restrict__ mask) {
    __shared__ float mts[DD];
    __shared__ float wt[256*33];
    int bx = blockIdx.x;
    int tid = threadIdx.x;
    if (bx < 69) {
        int sq = bx / 3;
        int c0 = (bx % 3) * 256;
        #pragma unroll
        for (int i = 0; i < 3; i++) mts[i*256 + tid] = mt[sq*DD + i*256 + tid];
        float acc = bias[c0 + tid];
        for (int k0 = 0; k0 < DD; k0 += 32) {
            __syncthreads();
            #pragma unroll
            for (int j = 0; j < 8; j++) {
                int idx = j*256 + tid;
                int c = idx >> 3;
                int kq = (idx & 7) * 4;
                float4 v = *(const float4*)(W + (size_t)(c0 + c)*DD + k0 + kq);
                float* d = wt + c*33 + kq;
                d[0] = v.x; d[1] = v.y; d[2] = v.z; d[3] = v.w;
            }
            __syncthreads();
            #pragma unroll
            for (int k = 0; k < 32; k++)
                acc += mts[k0 + k] * wt[tid*33 + k];
        }
        g_qconst[sq*DD + c0 + tid] = acc * rsqrtf((float)HDD);
    } else if (bx < 133) {
        int l = bx - 69;
        int d = tid;
        float a0 = 0.f, a1 = 0.f, a2 = 0.f;
        if (l < LL) {
            const float* pr = pw + l*DD;
            for (int j = 0; j < DD; j++) {
                float p = pr[j];
                const float* orow = ow + (size_t)j*DD;
                a0 += p*orow[d]; a1 += p*orow[d+256]; a2 += p*orow[d+512];
            }
        }
        g_Mt[d*NL + l] = a0;
        g_Mt[(d+256)*NL + l] = a1;
        g_Mt[(d+512)*NL + l] = a2;
    } else {
        int b = (bx - 133)*256 + tid;
        int c = 0;
        const int* mp = mask + b*SS;
        #pragma unroll
        for (int s = 0; s < SS; s++) c += (mp[s] != 0);
        g_nex[b] = c;
    }
}

// ================= PRE2: p2(192) + p5a(1) + fill(1) — k1 prerequisites only ========
#define PB_P2   192
#define PB_P5A  PB_P2              // 192 (single block)
#define PB_FILL (PB_P5A + 1)       // 193 (single block)
#define PB_GRID (PB_FILL + 1)      // 194

__global__ void __launch_bounds__(256) pre2(const float* __restrict__ W,
                                            const float* __restrict__ inb,
                                            const int* __restrict__ mask) {
    __shared__ float sh[128];
    __shared__ int wsums[8];
    int bx = blockIdx.x;
    int tid = threadIdx.x;

    if (bx < PB_P2) {
        int t = bx;
        __nv_bfloat16* dst = g_sprojh + (size_t)t*DD;
        if (t >= NT) {
            __nv_bfloat16 z = __float2bfloat16(0.f);
            dst[tid] = z; dst[tid+256] = z; dst[tid+512] = z;
            return;
        }
        int sq = t / HH, h = t - sq*HH;
        float* qs = sh;
        if (tid < HDD) qs[tid] = g_qconst[sq*DD + h*HDD + tid];
        __syncthreads();
        float a0 = 0.f, a1 = 0.f, a2 = 0.f;
        const float* Wb = W + (size_t)(DD + h*HDD)*DD + tid;
        #pragma unroll 8
        for (int j = 0; j < HDD; j++) {
            float q = qs[j];
            const float* wr = Wb + (size_t)j*DD;
            a0 += q * wr[0];
            a1 += q * wr[256];
            a2 += q * wr[512];
        }
        dst[tid]     = __float2bfloat16(a0);
        dst[tid+256] = __float2bfloat16(a1);
        dst[tid+512] = __float2bfloat16(a2);
    } else if (bx == PB_P5A) {
        if (tid >= NTP) return;
        float acc = 0.f;
        if (tid < NT) {
            int sq = tid / HH, h = tid % HH;
            for (int j = 0; j < HDD; j++)
                acc += g_qconst[sq*DD + h*HDD + j] * inb[DD + h*HDD + j];
        }
        g_c0[tid] = acc;
    } else {
        int b0 = tid * 8;
        int tot = 0;
        #pragma unroll
        for (int j = 0; j < 8; j++) tot += g_nex[b0 + j];
        int lane = tid & 31, w = tid >> 5;
        int v = tot;
        #pragma unroll
        for (int o = 1; o < 32; o <<= 1) {
            int x = __shfl_up_sync(0xFFFFFFFF, v, o);
            if (lane >= o) v += x;
        }
        if (lane == 31) wsums[w] = v;
        __syncthreads();
        int woff = 0;
        for (int i = 0; i < w; i++) woff += wsums[i];
        int p = woff + v - tot;
        #pragma unroll
        for (int j = 0; j < 8; j++) {
            int b = b0 + j;
            g_rowstart[b] = p;
            const int* mp = mask + b*SS;
            int jm = 0;
            for (int s = 0; s < SS; s++) {
                if (mp[s]) g_rowidx[p++] = b*SS + s;
                else g_sqmiss[b*24 + (jm++)] = s;
            }
        }
        if (tid == 255) {
            g_mtotal = p;
            for (int i = 0; i < 64; i++) g_rowidx[p + i] = 0;
        }
    }
}

// ---------------- K1: compacted scores GEMM (3-stage) + fused k3-weight prep -------
#define SKW 40
#define K1_ABUF 5120
#define K1_BBUF 15360
#define K1_STAGE (K1_ABUF + K1_BBUF)    // 20480
#define K1_RIDX (3*K1_STAGE)            // 61440
#define K1_SMEM (K1_RIDX + 256)         // 61696
#define K1_NCHUNK 24
#define K1_GEMM 736
#define K1_P4   (K1_GEMM + 192)         // 928
#define K1_P4T  (K1_P4 + 192)           // 1120
#define K1_GRID (K1_P4T + 64)           // 1184

__global__ void __launch_bounds__(256, 2) k1_mma(const float* __restrict__ cls,
                                                 const float* __restrict__ W,
                                                 const float* __restrict__ inb,
                                                 const float* __restrict__ pw,
                                                 const float* __restrict__ outb,
                                                 const float* __restrict__ mt) {
    extern __shared__ char smem[];
    int bx = blockIdx.x;
    int tid = threadIdx.x;

    if (bx >= K1_GEMM) {
        float* sh = (float*)smem;
        if (bx < K1_P4) {
            int b = bx - K1_GEMM;
            int h = b / 24, d0 = (b % 24) * 32;
            float* Mt_s = sh;
            float* W_s  = sh + 96*64;
            #pragma unroll
            for (int i = 0; i < 24; i++)
                Mt_s[i*256 + tid] = g_Mt[h*96*64 + i*256 + tid];
            #pragma unroll
            for (int i = 0; i < 12; i++) {
                int f = i*256 + tid;
                int t = f >> 5, j = f & 31;
                W_s[f] = W[(size_t)(2*DD + h*HDD + t)*DD + d0 + j];
            }
            __syncthreads();
            int d = tid & 31;
            int l0 = (tid >> 5) * 8;
            float acc[8];
            #pragma unroll
            for (int q = 0; q < 8; q++) acc[q] = 0.f;
            for (int t = 0; t < 96; t++) {
                float w = W_s[t*32 + d];
                float4 m0 = *(const float4*)(Mt_s + t*64 + l0);
                float4 m1 = *(const float4*)(Mt_s + t*64 + l0 + 4);
                acc[0] += m0.x*w; acc[1] += m0.y*w; acc[2] += m0.z*w; acc[3] += m0.w*w;
                acc[4] += m1.x*w; acc[5] += m1.y*w; acc[6] += m1.z*w; acc[7] += m1.w*w;
            }
            int col = h*DD + d0 + d;
            #pragma unroll
            for (int qq = 0; qq < 8; qq++) {
                int ll = l0 + qq;
                float x = acc[qq];
                __nv_bfloat16 hv = __float2bfloat16(x);
                __nv_bfloat16 lv = __float2bfloat16(x - __bfloat162float(hv));
                size_t off = (size_t)ll*KA + col;
                g_Wh[off] = hv;
                g_Wl[off] = lv;
            }
        } else if (bx < K1_P4T) {
            int idx = (bx - K1_P4)*256 + tid;
            int kk = idx % 768;
            int l = idx / 768;
            float x = (l < LL) ? pw[l*DD + kk] : 0.f;
            __nv_bfloat16 hv = __float2bfloat16(x);
            __nv_bfloat16 lv = __float2bfloat16(x - __bfloat162float(hv));
            size_t off = (size_t)l*KA + HH*DD + kk;
            g_Wh[off] = hv;
            g_Wl[off] = lv;
        } else {
            int l = bx - K1_P4T;
            float a = 0.f, b2 = 0.f, c = 0.f;
            if (l < LL) {
                for (int d = tid; d < DD; d += 256) {
                    float m = g_Mt[d*NL + l];
                    float p = pw[l*DD + d];
                    float ms = 0.f;
                    #pragma unroll
                    for (int s = 0; s < SS; s++) ms += mt[s*DD + d];
                    a += m * inb[2*DD + d];
                    b2 += p * outb[d];
                    c += p * ms;
                }
            }
            #pragma unroll
            for (int o = 16; o > 0; o >>= 1) {
                a += __shfl_down_sync(0xFFFFFFFF, a, o);
                b2 += __shfl_down_sync(0xFFFFFFFF, b2, o);
                c += __shfl_down_sync(0xFFFFFFFF, c, o);
            }
            float* red = sh;
            int w = tid >> 5, ln = tid & 31;
            if (ln == 0) { red[w] = a; red[8+w] = b2; red[16+w] = c; }
            __syncthreads();
            if (tid == 0) {
                float sa = 0.f, sb = 0.f, sc2 = 0.f;
                for (int i = 0; i < 8; i++) { sa += red[i]; sb += red[8+i]; sc2 += red[16+i]; }
                g_bvM[l] = sa; g_boutP[l] = sb; g_msumP[l] = sc2;
            }
        }
        return;
    }

    // ---------------- GEMM path ----------------
    uint32_t sb = smem_u32(smem);
    int* ridx = (int*)(smem + K1_RIDX);

    int wid = tid >> 5;
    int lane = tid & 31;
    int g = lane >> 2, t4 = lane & 3;
    int l16 = lane & 15, lhi = lane >> 4;
    int l8 = lane & 7, lm8 = (lane >> 3) & 1;

    int mtotal = g_mtotal;
    int m0 = bx * 64;
    if (m0 >= mtotal) return;

    if (tid < 64) ridx[tid] = g_rowidx[m0 + tid];
    __syncthreads();

    int wm = (wid & 1) * 32;
    int wn = (wid >> 1) * 48;

    int arow = tid >> 2, aq = tid & 3;
    const float* agp = cls + (size_t)ridx[arow]*DD + aq*8;
    uint32_t asts = (uint32_t)(arow*SKW + aq*8)*2;
    int br[3], bq[3];
    #pragma unroll
    for (int i = 0; i < 3; i++) { int f = i*256 + tid; br[i] = f >> 2; bq[i] = f & 3; }
    const __nv_bfloat16* bgp[3];
    uint32_t bsts[3];
    #pragma unroll
    for (int i = 0; i < 3; i++) {
        bgp[i] = g_sprojh + (size_t)br[i]*DD + bq[i]*8;
        bsts[i] = (uint32_t)K1_ABUF + (uint32_t)(br[i]*SKW + bq[i]*8)*2;
    }

    uint32_t aAddr = sb + ((wm + l16)*SKW + lhi*8)*2;
    uint32_t bAddr = sb + K1_ABUF + ((wn + l8 + lhi*8)*SKW + lm8*8)*2;

    float4 v0, v1; uint4 wb[3];
    {
        float4 a0 = *(const float4*)agp;
        float4 a1 = *(const float4*)(agp + 4);
        uint4 pk;
        pk.x = pack_bf16(a0.x, a0.y); pk.y = pack_bf16(a0.z, a0.w);
        pk.z = pack_bf16(a1.x, a1.y); pk.w = pack_bf16(a1.z, a1.w);
        *(uint4*)(smem + asts) = pk;
        #pragma unroll
        for (int i = 0; i < 3; i++)
            *(uint4*)(smem + bsts[i]) = *(const uint4*)bgp[i];
    }
    {
        v0 = *(const float4*)(agp + 32);
        v1 = *(const float4*)(agp + 36);
        #pragma unroll
        for (int i = 0; i < 3; i++)
            wb[i] = *(const uint4*)(bgp[i] + 32);
    }
    __syncthreads();

    float acc[2][6][4];
    #pragma unroll
    for (int i = 0; i < 2; i++)
        #pragma unroll
        for (int j = 0; j < 6; j++)
            #pragma unroll
            for (int q = 0; q < 4; q++) acc[i][j][q] = 0.f;

    for (int c = 0; c < K1_NCHUNK; c++) {
        if (c + 1 < K1_NCHUNK) {
            uint32_t so = ((c + 1) % 3) * K1_STAGE;
            uint4 pk;
            pk.x = pack_bf16(v0.x, v0.y); pk.y = pack_bf16(v0.z, v0.w);
            pk.z = pack_bf16(v1.x, v1.y); pk.w = pack_bf16(v1.z, v1.w);
            *(uint4*)(smem + so + asts) = pk;
            #pragma unroll
            for (int i = 0; i < 3; i++)
                *(uint4*)(smem + so + bsts[i]) = wb[i];
        }
        __syncthreads();
        if (c + 2 < K1_NCHUNK) {
            int kc = (c + 2) * 32;
            v0 = *(const float4*)(agp + kc);
            v1 = *(const float4*)(agp + kc + 4);
            #pragma unroll
            for (int i = 0; i < 3; i++)
                wb[i] = *(const uint4*)(bgp[i] + kc);
        }
        uint32_t st = (c % 3) * K1_STAGE;
        uint32_t aB = aAddr + st;
        uint32_t bB = bAddr + st;
        #pragma unroll
        for (int ks = 0; ks < 2; ks++) {
            uint32_t af[2][4];
            ldsm_x4(af[0][0], af[0][1], af[0][2], af[0][3], aB + ks*32);
            ldsm_x4(af[1][0], af[1][1], af[1][2], af[1][3], aB + 16*SKW*2 + ks*32);
            uint32_t bf[6][2];
            #pragma unroll
            for (int np = 0; np < 3; np++)
                ldsm_x4(bf[2*np][0], bf[2*np][1], bf[2*np+1][0], bf[2*np+1][1],
                        bB + np*16*SKW*2 + ks*32);
            #pragma unroll
            for (int mt2 = 0; mt2 < 2; mt2++)
                #pragma unroll
                for (int nt = 0; nt < 6; nt++)
                    mma_bf16(acc[mt2][nt], af[mt2][0], af[mt2][1], af[mt2][2], af[mt2][3],
                             bf[nt][0], bf[nt][1]);
        }
    }

    #pragma unroll
    for (int mt2 = 0; mt2 < 2; mt2++) {
        int m = m0 + wm + mt2*16 + g;
        float* row0 = g_scores + (size_t)m * NTP;
        float* row1 = row0 + 8*NTP;
        #pragma unroll
        for (int nt = 0; nt < 6; nt++) {
            int n = wn + nt*8 + 2*t4;
            float c00 = g_c0[n], c01 = g_c0[n+1];
            *(float2*)(row0 + n) = make_float2(acc[mt2][nt][0] + c00, acc[mt2][nt][1] + c01);
            *(float2*)(row1 + n) = make_float2(acc[mt2][nt][2] + c00, acc[mt2][nt][3] + c01);
        }
    }
}

// ---------------- K2 fused: softmax + wsm + u/csum with early cls prefetch ---------
__global__ void __launch_bounds__(256) k2f(const float* __restrict__ cls,
                                           const int* __restrict__ mask) {
    __shared__ float sc[SS][200];
    __shared__ float mx[NTP], den[NTP];
    __shared__ float wsm[HH*SS];
    __shared__ int e[SS], sklist[SS], sqm[SS];
    int b = blockIdx.x;
    int tid = threadIdx.x;

    int nex = g_nex[b];
    int rs = g_rowstart[b];
    int nmiss = SS - nex;

    if (tid < SS) {
        e[tid] = mask[b*SS + tid];
        sqm[tid] = g_sqmiss[b*24 + tid];
    }
    if (tid < nex) sklist[tid] = g_rowidx[rs + tid] - b*SS;
    for (int idx = tid; idx < nex*NTP; idx += 256)
        sc[idx / NTP][idx % NTP] = g_scores[(size_t)(rs + idx / NTP)*NTP + (idx % NTP)];
    __syncthreads();

    // prefetch first 4 cls rows for the u-phase BEFORE softmax compute
    float4 buf[4];
    const float* cbase = cls + (size_t)b*SS*DD + (tid & 255)*4;  // valid for tid<192 use
    if (tid < 192) {
        #pragma unroll
        for (int i = 0; i < 4; i++)
            if (i < nex) buf[i] = *(const float4*)(cbase + (size_t)sklist[i]*DD);
    }

    if (tid < NT) {
        int sq = tid >> 3;
        float m = -INFINITY, d = 0.f;
        if (nex > 0 && e[sq] == 0) {
            for (int i = 0; i < nex; i++) m = fmaxf(m, sc[i][tid]);
            for (int i = 0; i < nex; i++) d += __expf(sc[i][tid] - m);
        }
        mx[tid] = m; den[tid] = d;
    }
    __syncthreads();

    if (tid < HH*SS) {
        int h = tid / SS, i = tid - (tid/SS)*SS;
        float w = 0.f;
        if (i < nex) {
            for (int j = 0; j < nmiss; j++) {
                int t = sqm[j]*HH + h;
                w += __expf(sc[i][t] - mx[t]) / den[t];
            }
        }
        wsm[h*SS + i] = w;
    }
    __syncthreads();

    if (tid < 192) {
        int d0 = tid * 4;
        float4 u[HH];
        #pragma unroll
        for (int h = 0; h < HH; h++) u[h] = make_float4(0.f,0.f,0.f,0.f);
        float4 csum = make_float4(0.f,0.f,0.f,0.f);
        for (int i = 0; i < nex; i++) {
            float4 c = buf[i & 3];
            if (i + 4 < nex) buf[i & 3] = *(const float4*)(cbase + (size_t)sklist[i+4]*DD);
            csum.x += c.x; csum.y += c.y; csum.z += c.z; csum.w += c.w;
            #pragma unroll
            for (int h = 0; h < HH; h++) {
                float w = wsm[h*SS + i];
                u[h].x += w*c.x; u[h].y += w*c.y; u[h].z += w*c.z; u[h].w += w*c.w;
            }
        }
        __nv_bfloat16* ahrow = g_Ah + (size_t)b*KA + d0;
        __nv_bfloat16* alrow = g_Al + (size_t)b*KA + d0;
        #pragma unroll
        for (int h = 0; h < HH; h++)
            split_store4(ahrow + h*DD, alrow + h*DD, u[h]);
        split_store4(ahrow + HH*DD, alrow + HH*DD, csum);
    }
}

// ---------------- K3: split-bf16 logits GEMM via mma ----------------
#define K3_SKW 40
#define K3_BUF 5120
#define K3_AH 0
#define K3_AL K3_BUF
#define K3_WHO (2*K3_BUF)
#define K3_WLO (3*K3_BUF)
#define K3_STG (4*K3_BUF)
#define K3_NCHUNK 12

__global__ void __launch_bounds__(256) k3_mma() {
    __shared__ char smem[2*K3_STG];
    uint32_t sb = smem_u32(smem);
    int tid = threadIdx.x;
    int wid = tid >> 5, lane = tid & 31;
    int g = lane >> 2, t4 = lane & 3;
    int l16 = lane & 15, lhi = lane >> 4;
    int l8 = lane & 7, lm8 = (lane >> 3) & 1;
    int m0 = blockIdx.x * 64;
    int split = blockIdx.y;
    int k0 = split * 384;
    int wm = (wid & 1) * 32;
    int wn = (wid >> 1) * 16;

    int r = tid >> 2, q = tid & 3;
    const __nv_bfloat16* ahp = g_Ah + (size_t)(m0 + r)*KA + k0 + q*8;
    const __nv_bfloat16* alp = g_Al + (size_t)(m0 + r)*KA + k0 + q*8;
    const __nv_bfloat16* whp = g_Wh + (size_t)r*KA + k0 + q*8;
    const __nv_bfloat16* wlp = g_Wl + (size_t)r*KA + k0 + q*8;
    uint32_t sts = (uint32_t)(r*K3_SKW + q*8)*2;

    uint32_t aHb = sb + K3_AH + ((wm + l16)*K3_SKW + lhi*8)*2;
    uint32_t aLb = sb + K3_AL + ((wm + l16)*K3_SKW + lhi*8)*2;
    uint32_t bHb = sb + K3_WHO + ((wn + l8 + lhi*8)*K3_SKW + lm8*8)*2;
    uint32_t bLb = sb + K3_WLO + ((wn + l8 + lhi*8)*K3_SKW + lm8*8)*2;

    *(uint4*)(smem + K3_AH + sts) = *(const uint4*)ahp;
    *(uint4*)(smem + K3_AL + sts) = *(const uint4*)alp;
    *(uint4*)(smem + K3_WHO + sts) = *(const uint4*)whp;
    *(uint4*)(smem + K3_WLO + sts) = *(const uint4*)wlp;
    __syncthreads();

    float acc[2][2][4];
    #pragma unroll
    for (int i = 0; i < 2; i++)
        #pragma unroll
        for (int j = 0; j < 2; j++)
            #pragma unroll
            for (int p = 0; p < 4; p++) acc[i][j][p] = 0.f;

    for (int c = 0; c < K3_NCHUNK; c++) {
        int cb = c & 1;
        bool more = (c + 1 < K3_NCHUNK);
        uint4 va, vb, vc, vd;
        if (more) {
            int kc = (c + 1) * 32;
            va = *(const uint4*)(ahp + kc);
            vb = *(const uint4*)(alp + kc);
            vc = *(const uint4*)(whp + kc);
            vd = *(const uint4*)(wlp + kc);
        }
        uint32_t st = cb*K3_STG;
        #pragma unroll
        for (int ks = 0; ks < 2; ks++) {
            uint32_t ah0[4], ah1[4], al0[4], al1[4], wh[4], wl[4];
            ldsm_x4(ah0[0], ah0[1], ah0[2], ah0[3], aHb + st + ks*32);
            ldsm_x4(ah1[0], ah1[1], ah1[2], ah1[3], aHb + st + 16*K3_SKW*2 + ks*32);
            ldsm_x4(al0[0], al0[1], al0[2], al0[3], aLb + st + ks*32);
            ldsm_x4(al1[0], al1[1], al1[2], al1[3], aLb + st + 16*K3_SKW*2 + ks*32);
            ldsm_x4(wh[0], wh[1], wh[2], wh[3], bHb + st + ks*32);
            ldsm_x4(wl[0], wl[1], wl[2], wl[3], bLb + st + ks*32);
            mma_bf16(acc[0][0], ah0[0], ah0[1], ah0[2], ah0[3], wh[0], wh[1]);
            mma_bf16(acc[0][1], ah0[0], ah0[1], ah0[2], ah0[3], wh[2], wh[3]);
            mma_bf16(acc[1][0], ah1[0], ah1[1], ah1[2], ah1[3], wh[0], wh[1]);
            mma_bf16(acc[1][1], ah1[0], ah1[1], ah1[2], ah1[3], wh[2], wh[3]);
            mma_bf16(acc[0][0], ah0[0], ah0[1], ah0[2], ah0[3], wl[0], wl[1]);
            mma_bf16(acc[0][1], ah0[0], ah0[1], ah0[2], ah0[3], wl[2], wl[3]);
            mma_bf16(acc[1][0], ah1[0], ah1[1], ah1[2], ah1[3], wl[0], wl[1]);
            mma_bf16(acc[1][1], ah1[0], ah1[1], ah1[2], ah1[3], wl[2], wl[3]);
            mma_bf16(acc[0][0], al0[0], al0[1], al0[2], al0[3], wh[0], wh[1]);
            mma_bf16(acc[0][1], al0[0], al0[1], al0[2], al0[3], wh[2], wh[3]);
            mma_bf16(acc[1][0], al1[0], al1[1], al1[2], al1[3], wh[0], wh[1]);
            mma_bf16(acc[1][1], al1[0], al1[1], al1[2], al1[3], wh[2], wh[3]);
        }
        if (more) {
            uint32_t nst = ((c + 1) & 1)*K3_STG;
            *(uint4*)(smem + nst + K3_AH + sts) = va;
            *(uint4*)(smem + nst + K3_AL + sts) = vb;
            *(uint4*)(smem + nst + K3_WHO + sts) = vc;
            *(uint4*)(smem + nst + K3_WLO + sts) = vd;
            __syncthreads();
        }
    }

    #pragma unroll
    for (int mt = 0; mt < 2; mt++) {
        int m = m0 + wm + mt*16 + g;
        float* p0 = g_P + ((size_t)split*BB + m)*NL;
        float* p1 = p0 + 8*NL;
        #pragma unroll
        for (int nt = 0; nt < 2; nt++) {
            int n = wn + nt*8 + 2*t4;
            *(float2*)(p0 + n) = make_float2(acc[mt][nt][0], acc[mt][nt][1]);
            *(float2*)(p1 + n) = make_float2(acc[mt][nt][2], acc[mt][nt][3]);
        }
    }
}

// ---------------- K3b ----------------
__global__ void k3b_final(const int* __restrict__ mask, const float* __restrict__ pb,
                          float* __restrict__ out) {
    int idx = blockIdx.x*256 + threadIdx.x;
    if (idx >= BB*NL) return;
    int b = idx / NL, l = idx % NL;
    if (l >= LL) return;
    int nex = g_nex[b];
    float r;
    if (nex > 0) {
        float acc = 0.f;
        for (int s = 0; s < NSPLIT; s++)
            acc += g_P[((size_t)s*BB + b)*NL + l];
        float nmiss = (float)(SS - nex);
        r = (acc + nmiss*(g_bvM[l] + g_boutP[l])) * (1.f/SS) + pb[l];
    } else {
        r = g_msumP[l] * (1.f/SS) + pb[l];
    }
    out[b*LL + l] = r;
}

// ---------------- launcher ----------------
extern "C" void kernel_launch(void* const* d_in, const int* in_sizes, int n_in,
                              void* d_out, int out_size) {
    const float* cls  = (const float*)d_in[0];
    const int*   mask = (const int*)  d_in[1];
    const float* mt   = (const float*)d_in[2];
    const float* ipw  = (const float*)d_in[3];
    const float* ipb  = (const float*)d_in[4];
    const float* opw  = (const float*)d_in[5];
    const float* opb  = (const float*)d_in[6];
    const float* pw   = (const float*)d_in[7];
    const float* pb   = (const float*)d_in[8];
    float* out = (float*)d_out;

    cudaFuncSetAttribute(k1_mma, cudaFuncAttributeMaxDynamicSharedMemorySize, K1_SMEM);

    pre1<<<141, 256>>>(mt, ipw, ipb, pw, opw, mask);               // #1
    pre2<<<PB_GRID, 256>>>(ipw, ipb, mask);                        // #2
    k1_mma<<<K1_GRID, 256, K1_SMEM>>>(cls, ipw, ipb, pw, opb, mt); // #3
    k2f<<<BB, 256>>>(cls, mask);                                   // #4 -> profiled
    dim3 g3(32, NSPLIT);
    k3_mma<<<g3, 256>>>();                                         // #5
    k3b_final<<<(BB*NL + 255)/256, 256>>>(mask, pb, out);          // #6
}

// round 17
// speedup vs baseline: 1.0176x; 1.0176x over previous
#include <cuda_runtime.h>
#include <cuda_bf16.h>
#include <math.h>
#include <cstdint>

#define BB 2048
#define SS 23
#define DD 768
#define HH 8
#define HDD 96
#define LL 50
#define NT 184
#define NTP 192
#define KA 6912
#define NL 64
#define NSPLIT 18

// ---------------- scratch ----------------
__device__ float g_qconst[SS*DD];
__device__ __nv_bfloat16 g_sprojh[NTP*DD];
__device__ float g_c0[NTP];
__device__ float g_Mt[DD*NL];
__device__ float g_bvM[NL];
__device__ float g_boutP[NL];
__device__ float g_msumP[NL];
__device__ float g_scores[(size_t)BB*SS*NTP];
__device__ float g_wsmg[(size_t)BB*NTP];
__device__ __nv_bfloat16 g_Ah[(size_t)BB*KA];
__device__ __nv_bfloat16 g_Al[(size_t)BB*KA];
__device__ __nv_bfloat16 g_Wh[(size_t)NL*KA];   // [l][k]
__device__ __nv_bfloat16 g_Wl[(size_t)NL*KA];
__device__ float g_P[(size_t)NSPLIT*BB*NL];
// compaction
__device__ int g_rowidx[BB*SS + 64];
__device__ int g_rowstart[BB];
__device__ int g_nex[BB];
__device__ int g_sqmiss[BB*24];
__device__ int g_mtotal;

// ---------------- helpers ----------------
__device__ __forceinline__ uint32_t smem_u32(const void* p) {
    uint32_t a;
    asm("{ .reg .u64 t; cvta.to.shared.u64 t, %1; cvt.u32.u64 %0, t; }" : "=r"(a) : "l"(p));
    return a;
}
__device__ __forceinline__ void ldsm_x4(uint32_t& r0, uint32_t& r1, uint32_t& r2, uint32_t& r3,
                                        uint32_t addr) {
    asm volatile("ldmatrix.sync.aligned.m8n8.x4.shared.b16 {%0,%1,%2,%3}, [%4];"
                 : "=r"(r0), "=r"(r1), "=r"(r2), "=r"(r3) : "r"(addr));
}
__device__ __forceinline__ void mma_bf16(float* d,
                                         uint32_t a0, uint32_t a1, uint32_t a2, uint32_t a3,
                                         uint32_t b0, uint32_t b1) {
    asm volatile(
        "mma.sync.aligned.m16n8k16.row.col.f32.bf16.bf16.f32 "
        "{%0,%1,%2,%3}, {%4,%5,%6,%7}, {%8,%9}, {%0,%1,%2,%3};"
        : "+f"(d[0]), "+f"(d[1]), "+f"(d[2]), "+f"(d[3])
        : "r"(a0), "r"(a1), "r"(a2), "r"(a3), "r"(b0), "r"(b1));
}
__device__ __forceinline__ uint32_t pack_bf16(float lo, float hi) {
    __nv_bfloat162 v = __floats2bfloat162_rn(lo, hi);
    return *reinterpret_cast<uint32_t*>(&v);
}
__device__ __forceinline__ void split_store4(__nv_bfloat16* ph, __nv_bfloat16* pl, float4 v) {
    __nv_bfloat162 h0 = __floats2bfloat162_rn(v.x, v.y);
    __nv_bfloat162 h1 = __floats2bfloat162_rn(v.z, v.w);
    float2 f0 = __bfloat1622float2(h0);
    float2 f1 = __bfloat1622float2(h1);
    __nv_bfloat162 l0 = __floats2bfloat162_rn(v.x - f0.x, v.y - f0.y);
    __nv_bfloat162 l1 = __floats2bfloat162_rn(v.z - f1.x, v.w - f1.y);
    uint2 uh, ul;
    uh.x = *reinterpret_cast<uint32_t*>(&h0); uh.y = *reinterpret_cast<uint32_t*>(&h1);
    ul.x = *reinterpret_cast<uint32_t*>(&l0); ul.y = *reinterpret_cast<uint32_t*>(&l1);
    *(uint2*)ph = uh;
    *(uint2*)pl = ul;
}

// ================= PRE1: p1_qconst tiled (69) + p3_Mt (64) + nex-count (8) =========
__global__ void __launch_bounds__(256) pre1(const float* __restrict__ mt,
                                            const float* __restrict__ W,
                                            const float* __restrict__ bias,
                                            const float* __restrict__ pw,
                                            const float* __restrict__ ow,
                                            const int* __restrict__ mask) {
    __shared__ float mts[DD];
    __shared__ float wt[256*33];
    int bx = blockIdx.x;
    int tid = threadIdx.x;
    if (bx < 69) {
        int sq = bx / 3;
        int c0 = (bx % 3) * 256;
        #pragma unroll
        for (int i = 0; i < 3; i++) mts[i*256 + tid] = mt[sq*DD + i*256 + tid];
        float acc = bias[c0 + tid];
        for (int k0 = 0; k0 < DD; k0 += 32) {
            __syncthreads();
            #pragma unroll
            for (int j = 0; j < 8; j++) {
                int idx = j*256 + tid;
                int c = idx >> 3;
                int kq = (idx & 7) * 4;
                float4 v = *(const float4*)(W + (size_t)(c0 + c)*DD + k0 + kq);
                float* d = wt + c*33 + kq;
                d[0] = v.x; d[1] = v.y; d[2] = v.z; d[3] = v.w;
            }
            __syncthreads();
            #pragma unroll
            for (int k = 0; k < 32; k++)
                acc += mts[k0 + k] * wt[tid*33 + k];
        }
        g_qconst[sq*DD + c0 + tid] = acc * rsqrtf((float)HDD);
    } else if (bx < 133) {
        int l = bx - 69;
        int d = tid;
        float a0 = 0.f, a1 = 0.f, a2 = 0.f;
        if (l < LL) {
            const float* pr = pw + l*DD;
            for (int j = 0; j < DD; j++) {
                float p = pr[j];
                const float* orow = ow + (size_t)j*DD;
                a0 += p*orow[d]; a1 += p*orow[d+256]; a2 += p*orow[d+512];
            }
        }
        g_Mt[d*NL + l] = a0;
        g_Mt[(d+256)*NL + l] = a1;
        g_Mt[(d+512)*NL + l] = a2;
    } else {
        int b = (bx - 133)*256 + tid;
        int c = 0;
        const int* mp = mask + b*SS;
        #pragma unroll
        for (int s = 0; s < SS; s++) c += (mp[s] != 0);
        g_nex[b] = c;
    }
}

// ================= PRE2: p2(192) + p5a(1) + fill(1) — k1 prerequisites only ========
#define PB_P2   192
#define PB_P5A  PB_P2              // 192 (single block)
#define PB_FILL (PB_P5A + 1)       // 193 (single block)
#define PB_GRID (PB_FILL + 1)      // 194

__global__ void __launch_bounds__(256) pre2(const float* __restrict__ W,
                                            const float* __restrict__ inb,
                                            const int* __restrict__ mask) {
    __shared__ float sh[128];
    __shared__ int wsums[8];
    int bx = blockIdx.x;
    int tid = threadIdx.x;

    if (bx < PB_P2) {
        int t = bx;
        __nv_bfloat16* dst = g_sprojh + (size_t)t*DD;
        if (t >= NT) {
            __nv_bfloat16 z = __float2bfloat16(0.f);
            dst[tid] = z; dst[tid+256] = z; dst[tid+512] = z;
            return;
        }
        int sq = t / HH, h = t - sq*HH;
        float* qs = sh;
        if (tid < HDD) qs[tid] = g_qconst[sq*DD + h*HDD + tid];
        __syncthreads();
        float a0 = 0.f, a1 = 0.f, a2 = 0.f;
        const float* Wb = W + (size_t)(DD + h*HDD)*DD + tid;
        #pragma unroll 8
        for (int j = 0; j < HDD; j++) {
            float q = qs[j];
            const float* wr = Wb + (size_t)j*DD;
            a0 += q * wr[0];
            a1 += q * wr[256];
            a2 += q * wr[512];
        }
        dst[tid]     = __float2bfloat16(a0);
        dst[tid+256] = __float2bfloat16(a1);
        dst[tid+512] = __float2bfloat16(a2);
    } else if (bx == PB_P5A) {
        if (tid >= NTP) return;
        float acc = 0.f;
        if (tid < NT) {
            int sq = tid / HH, h = tid % HH;
            for (int j = 0; j < HDD; j++)
                acc += g_qconst[sq*DD + h*HDD + j] * inb[DD + h*HDD + j];
        }
        g_c0[tid] = acc;
    } else {
        int b0 = tid * 8;
        int tot = 0;
        #pragma unroll
        for (int j = 0; j < 8; j++) tot += g_nex[b0 + j];
        int lane = tid & 31, w = tid >> 5;
        int v = tot;
        #pragma unroll
        for (int o = 1; o < 32; o <<= 1) {
            int x = __shfl_up_sync(0xFFFFFFFF, v, o);
            if (lane >= o) v += x;
        }
        if (lane == 31) wsums[w] = v;
        __syncthreads();
        int woff = 0;
        for (int i = 0; i < w; i++) woff += wsums[i];
        int p = woff + v - tot;
        #pragma unroll
        for (int j = 0; j < 8; j++) {
            int b = b0 + j;
            g_rowstart[b] = p;
            const int* mp = mask + b*SS;
            int jm = 0;
            for (int s = 0; s < SS; s++) {
                if (mp[s]) g_rowidx[p++] = b*SS + s;
                else g_sqmiss[b*24 + (jm++)] = s;
            }
        }
        if (tid == 255) {
            g_mtotal = p;
            for (int i = 0; i < 64; i++) g_rowidx[p + i] = 0;
        }
    }
}

// ---------------- K1: compacted scores GEMM (3-stage) + fused k3-weight prep -------
#define SKW 40
#define K1_ABUF 5120
#define K1_BBUF 15360
#define K1_STAGE (K1_ABUF + K1_BBUF)    // 20480
#define K1_RIDX (3*K1_STAGE)            // 61440
#define K1_SMEM (K1_RIDX + 256)         // 61696
#define K1_NCHUNK 24
#define K1_GEMM 736
#define K1_P4   (K1_GEMM + 192)         // 928
#define K1_P4T  (K1_P4 + 192)           // 1120
#define K1_GRID (K1_P4T + 64)           // 1184

__global__ void __launch_bounds__(256, 2) k1_mma(const float* __restrict__ cls,
                                                 const float* __restrict__ W,
                                                 const float* __restrict__ inb,
                                                 const float* __restrict__ pw,
                                                 const float* __restrict__ outb,
                                                 const float* __restrict__ mt) {
    extern __shared__ char smem[];
    int bx = blockIdx.x;
    int tid = threadIdx.x;

    if (bx >= K1_GEMM) {
        float* sh = (float*)smem;
        if (bx < K1_P4) {
            int b = bx - K1_GEMM;
            int h = b / 24, d0 = (b % 24) * 32;
            float* Mt_s = sh;
            float* W_s  = sh + 96*64;
            #pragma unroll
            for (int i = 0; i < 24; i++)
                Mt_s[i*256 + tid] = g_Mt[h*96*64 + i*256 + tid];
            #pragma unroll
            for (int i = 0; i < 12; i++) {
                int f = i*256 + tid;
                int t = f >> 5, j = f & 31;
                W_s[f] = W[(size_t)(2*DD + h*HDD + t)*DD + d0 + j];
            }
            __syncthreads();
            int d = tid & 31;
            int l0 = (tid >> 5) * 8;
            float acc[8];
            #pragma unroll
            for (int q = 0; q < 8; q++) acc[q] = 0.f;
            for (int t = 0; t < 96; t++) {
                float w = W_s[t*32 + d];
                float4 m0 = *(const float4*)(Mt_s + t*64 + l0);
                float4 m1 = *(const float4*)(Mt_s + t*64 + l0 + 4);
                acc[0] += m0.x*w; acc[1] += m0.y*w; acc[2] += m0.z*w; acc[3] += m0.w*w;
                acc[4] += m1.x*w; acc[5] += m1.y*w; acc[6] += m1.z*w; acc[7] += m1.w*w;
            }
            int col = h*DD + d0 + d;
            #pragma unroll
            for (int qq = 0; qq < 8; qq++) {
                int ll = l0 + qq;
                float x = acc[qq];
                __nv_bfloat16 hv = __float2bfloat16(x);
                __nv_bfloat16 lv = __float2bfloat16(x - __bfloat162float(hv));
                size_t off = (size_t)ll*KA + col;
                g_Wh[off] = hv;
                g_Wl[off] = lv;
            }
        } else if (bx < K1_P4T) {
            int idx = (bx - K1_P4)*256 + tid;
            int kk = idx % 768;
            int l = idx / 768;
            float x = (l < LL) ? pw[l*DD + kk] : 0.f;
            __nv_bfloat16 hv = __float2bfloat16(x);
            __nv_bfloat16 lv = __float2bfloat16(x - __bfloat162float(hv));
            size_t off = (size_t)l*KA + HH*DD + kk;
            g_Wh[off] = hv;
            g_Wl[off] = lv;
        } else {
            int l = bx - K1_P4T;
            float a = 0.f, b2 = 0.f, c = 0.f;
            if (l < LL) {
                for (int d = tid; d < DD; d += 256) {
                    float m = g_Mt[d*NL + l];
                    float p = pw[l*DD + d];
                    float ms = 0.f;
                    #pragma unroll
                    for (int s = 0; s < SS; s++) ms += mt[s*DD + d];
                    a += m * inb[2*DD + d];
                    b2 += p * outb[d];
                    c += p * ms;
                }
            }
            #pragma unroll
            for (int o = 16; o > 0; o >>= 1) {
                a += __shfl_down_sync(0xFFFFFFFF, a, o);
                b2 += __shfl_down_sync(0xFFFFFFFF, b2, o);
                c += __shfl_down_sync(0xFFFFFFFF, c, o);
            }
            float* red = sh;
            int w = tid >> 5, ln = tid & 31;
            if (ln == 0) { red[w] = a; red[8+w] = b2; red[16+w] = c; }
            __syncthreads();
            if (tid == 0) {
                float sa = 0.f, sb = 0.f, sc2 = 0.f;
                for (int i = 0; i < 8; i++) { sa += red[i]; sb += red[8+i]; sc2 += red[16+i]; }
                g_bvM[l] = sa; g_boutP[l] = sb; g_msumP[l] = sc2;
            }
        }
        return;
    }

    // ---------------- GEMM path ----------------
    uint32_t sb = smem_u32(smem);
    int* ridx = (int*)(smem + K1_RIDX);

    int wid = tid >> 5;
    int lane = tid & 31;
    int g = lane >> 2, t4 = lane & 3;
    int l16 = lane & 15, lhi = lane >> 4;
    int l8 = lane & 7, lm8 = (lane >> 3) & 1;

    int mtotal = g_mtotal;
    int m0 = bx * 64;
    if (m0 >= mtotal) return;

    if (tid < 64) ridx[tid] = g_rowidx[m0 + tid];
    __syncthreads();

    int wm = (wid & 1) * 32;
    int wn = (wid >> 1) * 48;

    int arow = tid >> 2, aq = tid & 3;
    const float* agp = cls + (size_t)ridx[arow]*DD + aq*8;
    uint32_t asts = (uint32_t)(arow*SKW + aq*8)*2;
    int br[3], bq[3];
    #pragma unroll
    for (int i = 0; i < 3; i++) { int f = i*256 + tid; br[i] = f >> 2; bq[i] = f & 3; }
    const __nv_bfloat16* bgp[3];
    uint32_t bsts[3];
    #pragma unroll
    for (int i = 0; i < 3; i++) {
        bgp[i] = g_sprojh + (size_t)br[i]*DD + bq[i]*8;
        bsts[i] = (uint32_t)K1_ABUF + (uint32_t)(br[i]*SKW + bq[i]*8)*2;
    }

    uint32_t aAddr = sb + ((wm + l16)*SKW + lhi*8)*2;
    uint32_t bAddr = sb + K1_ABUF + ((wn + l8 + lhi*8)*SKW + lm8*8)*2;

    float4 v0, v1; uint4 wb[3];
    {
        float4 a0 = *(const float4*)agp;
        float4 a1 = *(const float4*)(agp + 4);
        uint4 pk;
        pk.x = pack_bf16(a0.x, a0.y); pk.y = pack_bf16(a0.z, a0.w);
        pk.z = pack_bf16(a1.x, a1.y); pk.w = pack_bf16(a1.z, a1.w);
        *(uint4*)(smem + asts) = pk;
        #pragma unroll
        for (int i = 0; i < 3; i++)
            *(uint4*)(smem + bsts[i]) = *(const uint4*)bgp[i];
    }
    {
        v0 = *(const float4*)(agp + 32);
        v1 = *(const float4*)(agp + 36);
        #pragma unroll
        for (int i = 0; i < 3; i++)
            wb[i] = *(const uint4*)(bgp[i] + 32);
    }
    __syncthreads();

    float acc[2][6][4];
    #pragma unroll
    for (int i = 0; i < 2; i++)
        #pragma unroll
        for (int j = 0; j < 6; j++)
            #pragma unroll
            for (int q = 0; q < 4; q++) acc[i][j][q] = 0.f;

    for (int c = 0; c < K1_NCHUNK; c++) {
        if (c + 1 < K1_NCHUNK) {
            uint32_t so = ((c + 1) % 3) * K1_STAGE;
            uint4 pk;
            pk.x = pack_bf16(v0.x, v0.y); pk.y = pack_bf16(v0.z, v0.w);
            pk.z = pack_bf16(v1.x, v1.y); pk.w = pack_bf16(v1.z, v1.w);
            *(uint4*)(smem + so + asts) = pk;
            #pragma unroll
            for (int i = 0; i < 3; i++)
                *(uint4*)(smem + so + bsts[i]) = wb[i];
        }
        __syncthreads();
        if (c + 2 < K1_NCHUNK) {
            int kc = (c + 2) * 32;
            v0 = *(const float4*)(agp + kc);
            v1 = *(const float4*)(agp + kc + 4);
            #pragma unroll
            for (int i = 0; i < 3; i++)
                wb[i] = *(const uint4*)(bgp[i] + kc);
        }
        uint32_t st = (c % 3) * K1_STAGE;
        uint32_t aB = aAddr + st;
        uint32_t bB = bAddr + st;
        #pragma unroll
        for (int ks = 0; ks < 2; ks++) {
            uint32_t af[2][4];
            ldsm_x4(af[0][0], af[0][1], af[0][2], af[0][3], aB + ks*32);
            ldsm_x4(af[1][0], af[1][1], af[1][2], af[1][3], aB + 16*SKW*2 + ks*32);
            uint32_t bf[6][2];
            #pragma unroll
            for (int np = 0; np < 3; np++)
                ldsm_x4(bf[2*np][0], bf[2*np][1], bf[2*np+1][0], bf[2*np+1][1],
                        bB + np*16*SKW*2 + ks*32);
            #pragma unroll
            for (int mt2 = 0; mt2 < 2; mt2++)
                #pragma unroll
                for (int nt = 0; nt < 6; nt++)
                    mma_bf16(acc[mt2][nt], af[mt2][0], af[mt2][1], af[mt2][2], af[mt2][3],
                             bf[nt][0], bf[nt][1]);
        }
    }

    #pragma unroll
    for (int mt2 = 0; mt2 < 2; mt2++) {
        int m = m0 + wm + mt2*16 + g;
        float* row0 = g_scores + (size_t)m * NTP;
        float* row1 = row0 + 8*NTP;
        #pragma unroll
        for (int nt = 0; nt < 6; nt++) {
            int n = wn + nt*8 + 2*t4;
            float c00 = g_c0[n], c01 = g_c0[n+1];
            *(float2*)(row0 + n) = make_float2(acc[mt2][nt][0] + c00, acc[mt2][nt][1] + c01);
            *(float2*)(row1 + n) = make_float2(acc[mt2][nt][2] + c00, acc[mt2][nt][3] + c01);
        }
    }
}

// ---------------- K2a: softmax -> wsm (exp cached in-place, reciprocal den) --------
__global__ void __launch_bounds__(256) k2a(const int* __restrict__ mask) {
    __shared__ float sc[SS][200];
    __shared__ float den[NTP];
    __shared__ int e[SS], sqm[SS];
    int b = blockIdx.x;
    int tid = threadIdx.x;

    int nex = g_nex[b];
    int rs = g_rowstart[b];
    int nmiss = SS - nex;

    if (tid < SS) {
        e[tid] = mask[b*SS + tid];
        sqm[tid] = g_sqmiss[b*24 + tid];
    }
    for (int idx = tid; idx < nex*NTP; idx += 256)
        sc[idx / NTP][idx % NTP] = g_scores[(size_t)(rs + idx / NTP)*NTP + (idx % NTP)];
    __syncthreads();

    if (tid < NT) {
        int sq = tid >> 3;
        float rd = 0.f;
        if (nex > 0 && e[sq] == 0) {
            float m = -INFINITY;
            for (int i = 0; i < nex; i++) m = fmaxf(m, sc[i][tid]);
            float d = 0.f;
            for (int i = 0; i < nex; i++) {
                float ex = __expf(sc[i][tid] - m);
                sc[i][tid] = ex;           // cache exp in place
                d += ex;
            }
            rd = __frcp_rn(d);
        }
        den[tid] = rd;
    }
    __syncthreads();

    if (tid < HH*SS) {
        int h = tid / SS, i = tid - (tid/SS)*SS;
        float w = 0.f;
        if (i < nex) {
            for (int j = 0; j < nmiss; j++) {
                int t = sqm[j]*HH + h;
                w += sc[i][t] * den[t];    // pure FMA — no exp, no div
            }
        }
        g_wsmg[(size_t)b*NTP + h*SS + i] = w;
    }
}

// ---------------- K2b: u/csum GEMV ----------------
__global__ void __launch_bounds__(192) k2b(const float* __restrict__ cls) {
    __shared__ float wsm[HH*SS];
    __shared__ int sklist[SS];
    int b = blockIdx.x;
    int tid = threadIdx.x;
    int nex = g_nex[b];
    int rs = g_rowstart[b];

    if (tid < HH*SS) wsm[tid] = g_wsmg[(size_t)b*NTP + tid];
    if (tid < nex) sklist[tid] = g_rowidx[rs + tid] - b*SS;
    __syncthreads();

    int d0 = tid * 4;
    const float* cbase = cls + (size_t)b*SS*DD + d0;
    float4 u[HH];
    #pragma unroll
    for (int h = 0; h < HH; h++) u[h] = make_float4(0.f,0.f,0.f,0.f);
    float4 csum = make_float4(0.f,0.f,0.f,0.f);
    float4 buf[4];
    #pragma unroll
    for (int i = 0; i < 4; i++)
        if (i < nex) buf[i] = *(const float4*)(cbase + (size_t)sklist[i]*DD);
    for (int i = 0; i < nex; i++) {
        float4 c = buf[i & 3];
        if (i + 4 < nex) buf[i & 3] = *(const float4*)(cbase + (size_t)sklist[i+4]*DD);
        csum.x += c.x; csum.y += c.y; csum.z += c.z; csum.w += c.w;
        #pragma unroll
        for (int h = 0; h < HH; h++) {
            float w = wsm[h*SS + i];
            u[h].x += w*c.x; u[h].y += w*c.y; u[h].z += w*c.z; u[h].w += w*c.w;
        }
    }
    __nv_bfloat16* ahrow = g_Ah + (size_t)b*KA + d0;
    __nv_bfloat16* alrow = g_Al + (size_t)b*KA + d0;
    #pragma unroll
    for (int h = 0; h < HH; h++)
        split_store4(ahrow + h*DD, alrow + h*DD, u[h]);
    split_store4(ahrow + HH*DD, alrow + HH*DD, csum);
}

// ---------------- K3: split-bf16 logits GEMM via mma ----------------
#define K3_SKW 40
#define K3_BUF 5120
#define K3_AH 0
#define K3_AL K3_BUF
#define K3_WHO (2*K3_BUF)
#define K3_WLO (3*K3_BUF)
#define K3_STG (4*K3_BUF)
#define K3_NCHUNK 12

__global__ void __launch_bounds__(256) k3_mma() {
    __shared__ char smem[2*K3_STG];
    uint32_t sb = smem_u32(smem);
    int tid = threadIdx.x;
    int wid = tid >> 5, lane = tid & 31;
    int g = lane >> 2, t4 = lane & 3;
    int l16 = lane & 15, lhi = lane >> 4;
    int l8 = lane & 7, lm8 = (lane >> 3) & 1;
    int m0 = blockIdx.x * 64;
    int split = blockIdx.y;
    int k0 = split * 384;
    int wm = (wid & 1) * 32;
    int wn = (wid >> 1) * 16;

    int r = tid >> 2, q = tid & 3;
    const __nv_bfloat16* ahp = g_Ah + (size_t)(m0 + r)*KA + k0 + q*8;
    const __nv_bfloat16* alp = g_Al + (size_t)(m0 + r)*KA + k0 + q*8;
    const __nv_bfloat16* whp = g_Wh + (size_t)r*KA + k0 + q*8;
    const __nv_bfloat16* wlp = g_Wl + (size_t)r*KA + k0 + q*8;
    uint32_t sts = (uint32_t)(r*K3_SKW + q*8)*2;

    uint32_t aHb = sb + K3_AH + ((wm + l16)*K3_SKW + lhi*8)*2;
    uint32_t aLb = sb + K3_AL + ((wm + l16)*K3_SKW + lhi*8)*2;
    uint32_t bHb = sb + K3_WHO + ((wn + l8 + lhi*8)*K3_SKW + lm8*8)*2;
    uint32_t bLb = sb + K3_WLO + ((wn + l8 + lhi*8)*K3_SKW + lm8*8)*2;

    *(uint4*)(smem + K3_AH + sts) = *(const uint4*)ahp;
    *(uint4*)(smem + K3_AL + sts) = *(const uint4*)alp;
    *(uint4*)(smem + K3_WHO + sts) = *(const uint4*)whp;
    *(uint4*)(smem + K3_WLO + sts) = *(const uint4*)wlp;
    __syncthreads();

    float acc[2][2][4];
    #pragma unroll
    for (int i = 0; i < 2; i++)
        #pragma unroll
        for (int j = 0; j < 2; j++)
            #pragma unroll
            for (int p = 0; p < 4; p++) acc[i][j][p] = 0.f;

    for (int c = 0; c < K3_NCHUNK; c++) {
        int cb = c & 1;
        bool more = (c + 1 < K3_NCHUNK);
        uint4 va, vb, vc, vd;
        if (more) {
            int kc = (c + 1) * 32;
            va = *(const uint4*)(ahp + kc);
            vb = *(const uint4*)(alp + kc);
            vc = *(const uint4*)(whp + kc);
            vd = *(const uint4*)(wlp + kc);
        }
        uint32_t st = cb*K3_STG;
        #pragma unroll
        for (int ks = 0; ks < 2; ks++) {
            uint32_t ah0[4], ah1[4], al0[4], al1[4], wh[4], wl[4];
            ldsm_x4(ah0[0], ah0[1], ah0[2], ah0[3], aHb + st + ks*32);
            ldsm_x4(ah1[0], ah1[1], ah1[2], ah1[3], aHb + st + 16*K3_SKW*2 + ks*32);
            ldsm_x4(al0[0], al0[1], al0[2], al0[3], aLb + st + ks*32);
            ldsm_x4(al1[0], al1[1], al1[2], al1[3], aLb + st + 16*K3_SKW*2 + ks*32);
            ldsm_x4(wh[0], wh[1], wh[2], wh[3], bHb + st + ks*32);
            ldsm_x4(wl[0], wl[1], wl[2], wl[3], bLb + st + ks*32);
            mma_bf16(acc[0][0], ah0[0], ah0[1], ah0[2], ah0[3], wh[0], wh[1]);
            mma_bf16(acc[0][1], ah0[0], ah0[1], ah0[2], ah0[3], wh[2], wh[3]);
            mma_bf16(acc[1][0], ah1[0], ah1[1], ah1[2], ah1[3], wh[0], wh[1]);
            mma_bf16(acc[1][1], ah1[0], ah1[1], ah1[2], ah1[3], wh[2], wh[3]);
            mma_bf16(acc[0][0], ah0[0], ah0[1], ah0[2], ah0[3], wl[0], wl[1]);
            mma_bf16(acc[0][1], ah0[0], ah0[1], ah0[2], ah0[3], wl[2], wl[3]);
            mma_bf16(acc[1][0], ah1[0], ah1[1], ah1[2], ah1[3], wl[0], wl[1]);
            mma_bf16(acc[1][1], ah1[0], ah1[1], ah1[2], ah1[3], wl[2], wl[3]);
            mma_bf16(acc[0][0], al0[0], al0[1], al0[2], al0[3], wh[0], wh[1]);
            mma_bf16(acc[0][1], al0[0], al0[1], al0[2], al0[3], wh[2], wh[3]);
            mma_bf16(acc[1][0], al1[0], al1[1], al1[2], al1[3], wh[0], wh[1]);
            mma_bf16(acc[1][1], al1[0], al1[1], al1[2], al1[3], wh[2], wh[3]);
        }
        if (more) {
            uint32_t nst = ((c + 1) & 1)*K3_STG;
            *(uint4*)(smem + nst + K3_AH + sts) = va;
            *(uint4*)(smem + nst + K3_AL + sts) = vb;
            *(uint4*)(smem + nst + K3_WHO + sts) = vc;
            *(uint4*)(smem + nst + K3_WLO + sts) = vd;
            __syncthreads();
        }
    }

    #pragma unroll
    for (int mt = 0; mt < 2; mt++) {
        int m = m0 + wm + mt*16 + g;
        float* p0 = g_P + ((size_t)split*BB + m)*NL;
        float* p1 = p0 + 8*NL;
        #pragma unroll
        for (int nt = 0; nt < 2; nt++) {
            int n = wn + nt*8 + 2*t4;
            *(float2*)(p0 + n) = make_float2(acc[mt][nt][0], acc[mt][nt][1]);
            *(float2*)(p1 + n) = make_float2(acc[mt][nt][2], acc[mt][nt][3]);
        }
    }
}

// ---------------- K3b ----------------
__global__ void k3b_final(const int* __restrict__ mask, const float* __restrict__ pb,
                          float* __restrict__ out) {
    int idx = blockIdx.x*256 + threadIdx.x;
    if (idx >= BB*NL) return;
    int b = idx / NL, l = idx % NL;
    if (l >= LL) return;
    int nex = g_nex[b];
    float r;
    if (nex > 0) {
        float acc = 0.f;
        for (int s = 0; s < NSPLIT; s++)
            acc += g_P[((size_t)s*BB + b)*NL + l];
        float nmiss = (float)(SS - nex);
        r = (acc + nmiss*(g_bvM[l] + g_boutP[l])) * (1.f/SS) + pb[l];
    } else {
        r = g_msumP[l] * (1.f/SS) + pb[l];
    }
    out[b*LL + l] = r;
}

// ---------------- launcher ----------------
extern "C" void kernel_launch(void* const* d_in, const int* in_sizes, int n_in,
                              void* d_out, int out_size) {
    const float* cls  = (const float*)d_in[0];
    const int*   mask = (const int*)  d_in[1];
    const float* mt   = (const float*)d_in[2];
    const float* ipw  = (const float*)d_in[3];
    const float* ipb  = (const float*)d_in[4];
    const float* opw  = (const float*)d_in[5];
    const float* opb  = (const float*)d_in[6];
    const float* pw   = (const float*)d_in[7];
    const float* pb   = (const float*)d_in[8];
    float* out = (float*)d_out;

    cudaFuncSetAttribute(k1_mma, cudaFuncAttributeMaxDynamicSharedMemorySize, K1_SMEM);

    pre1<<<141, 256>>>(mt, ipw, ipb, pw, opw, mask);               // #1
    pre2<<<PB_GRID, 256>>>(ipw, ipb, mask);                        // #2
    k1_mma<<<K1_GRID, 256, K1_SMEM>>>(cls, ipw, ipb, pw, opb, mt); // #3
    k2a<<<BB, 256>>>(mask);                                        // #4 -> profiled
    k2b<<<BB, 192>>>(cls);                                         // #5
    dim3 g3(32, NSPLIT);
    k3_mma<<<g3, 256>>>();                                         // #6
    k3b_final<<<(BB*NL + 255)/256, 256>>>(mask, pb, out);          // #7
}